// round 3
// baseline (speedup 1.0000x reference)
#include <cuda_runtime.h>
#include <math.h>

// ---------------- problem constants ----------------
#define BB   128
#define TT   1024
#define II   256
#define HH   512
#define OO   256
#define LOUT 64
#define NCTA 128          // persistent grid; <= 148 SMs, 1 CTA/SM -> all co-resident

#define HP   514          // padded h row stride (floats) in smem
#define XS   130          // padded xproj smem row stride (floats), K-chunk = 128

// smem sizes (bytes)
#define XPROJ_SMEM (2 * 64 * XS * 4)                                 // 66560
#define RNN_FLOATS (8*HP + 4*512 + 32*HP + 512 + 512 + 256)          // 23888
#define RNN_SMEM   (RNN_FLOATS * 4)                                  // 95552

// ---------------- device scratch (static; no runtime allocation) ----------------
__device__ float g_xproj[(size_t)BB * TT * HH];   // 256 MB: x @ W_ih^T + b_ih
__device__ float g_hbuf[2][BB * HH];              // double-buffered hidden state
__device__ int            g_count = 0;
__device__ volatile unsigned g_gen = 0;

union U64 { unsigned long long u; float2 f; };

// Blackwell packed fp32 FMA (2 FMAs/instr; ptxas never auto-emits this)
__device__ __forceinline__ void ffma2(U64 &d, U64 a, U64 b) {
    asm("fma.rn.f32x2 %0, %1, %2, %0;" : "+l"(d.u) : "l"(a.u), "l"(b.u));
}

// Grid-wide sense barrier. Self-resetting count, monotonic generation ->
// safe across CUDA-graph replays. All NCTA CTAs are wave-1 resident.
__device__ __forceinline__ void grid_barrier() {
    __syncthreads();
    if (threadIdx.x == 0) {
        unsigned my = g_gen;                 // read BEFORE arriving
        __threadfence();                     // release our L2 (stcg) writes
        int prev = atomicAdd(&g_count, 1);
        if (prev == NCTA - 1) {
            atomicExch(&g_count, 0);
            __threadfence();
            g_gen = my + 1;
        } else {
            while (g_gen == my) { __nanosleep(64); }
        }
        __threadfence();                     // acquire
    }
    __syncthreads();
}

// ============================================================================
// Kernel 1: x_proj[b,t,h] = x[b,t,:] . W_ih[h,:] + b_ih[h]
// Tile 64(t) x 64(h), K in 2 chunks of 128 staged in smem, 256 thr, 4x4 microtile.
// Tiles with t0 >= lengths[b] are skipped (their output is never read).
// ============================================================================
__global__ void __launch_bounds__(256, 2)
k_xproj(const float* __restrict__ x, const int* __restrict__ lengths,
        const float* __restrict__ W_ih, const float* __restrict__ b_ih)
{
    extern __shared__ float sm[];
    float* xs = sm;                // [64][XS]
    float* ws = sm + 64 * XS;      // [64][XS]

    const int b  = blockIdx.z;
    const int t0 = blockIdx.y * 64;
    const int h0 = blockIdx.x * 64;
    if (t0 >= lengths[b]) return;

    const int tid = threadIdx.x;
    const int tr  = tid >> 4;      // 0..15
    const int tc  = tid & 15;      // 0..15

    U64 acc[4][4];
    #pragma unroll
    for (int i = 0; i < 4; i++)
        #pragma unroll
        for (int j = 0; j < 4; j++) acc[i][j].u = 0ULL;

    for (int kc = 0; kc < 2; kc++) {
        __syncthreads();
        #pragma unroll
        for (int i = 0; i < 16; i++) {          // 4096 float2 per operand tile
            int e = tid + 256 * i;
            int r = e >> 6, cc = e & 63;        // 64 float2 per row
            float2 xv = *(const float2*)(x + ((size_t)b * TT + t0 + r) * II + kc * 128 + 2 * cc);
            *(float2*)(xs + r * XS + 2 * cc) = xv;
            float2 wv = *(const float2*)(W_ih + (size_t)(h0 + r) * II + kc * 128 + 2 * cc);
            *(float2*)(ws + r * XS + 2 * cc) = wv;
        }
        __syncthreads();
        #pragma unroll 4
        for (int kp = 0; kp < 64; kp++) {
            U64 xf[4], wf[4];
            #pragma unroll
            for (int i = 0; i < 4; i++) xf[i].f = *(const float2*)(xs + (tr + 16*i) * XS + 2 * kp);
            #pragma unroll
            for (int j = 0; j < 4; j++) wf[j].f = *(const float2*)(ws + (tc + 16*j) * XS + 2 * kp);
            #pragma unroll
            for (int i = 0; i < 4; i++)
                #pragma unroll
                for (int j = 0; j < 4; j++) ffma2(acc[i][j], xf[i], wf[j]);
        }
    }

    #pragma unroll
    for (int i = 0; i < 4; i++)
        #pragma unroll
        for (int j = 0; j < 4; j++) {
            int t = t0 + tr + 16 * i;
            int h = h0 + tc + 16 * j;
            g_xproj[((size_t)b * TT + t) * HH + h] = acc[i][j].f.x + acc[i][j].f.y + b_ih[h];
        }
}

// ============================================================================
// Kernel 2: persistent encoder (1024 steps) + decoder (64 steps).
// 128 CTAs: CTA (rg,cg) owns rows b = rg*8..+8, cols h = cg*64..+64.
// Thread t: c = t&63 (col), kq = t>>6 (k-quarter). W_hh slice lives in
// 64 U64 registers for the whole kernel. h via L2 (__ldcg/__stcg).
// ============================================================================
__global__ void __launch_bounds__(256, 1)
k_rnn(const int* __restrict__ lengths, const float* __restrict__ W_hh,
      const float* __restrict__ b_hh, const float* __restrict__ b_ih,
      const float* __restrict__ W_out, const float* __restrict__ b_out,
      float* __restrict__ out)
{
    extern __shared__ float sm[];
    float* hs    = sm;                 // [8][HP]   staged h rows
    float* part  = sm + 8 * HP;        // [4][512]  k-split partials
    float* wouts = part + 4 * 512;     // [32][HP]  W_out slice
    float* sbhh  = wouts + 32 * HP;    // [512]
    float* sbih  = sbhh + 512;         // [512]
    float* sbout = sbih + 512;         // [256]

    const int tid    = threadIdx.x;
    const int cta    = blockIdx.x;
    const int rg     = cta >> 3;       // 0..15
    const int cg     = cta & 7;        // 0..7
    const int c      = tid & 63;
    const int kq     = tid >> 6;       // 0..3
    const int b_base = rg * 8;
    const int col_c  = cg * 64 + c;
    const int r0     = tid >> 6;       // rows r0 and r0+4 in reduce phase

    // --- W_hh slice -> registers (permanent) ---
    U64 W[64];
    {
        const float2* wsrc = (const float2*)(W_hh + (size_t)col_c * HH + kq * 128);
        #pragma unroll
        for (int j = 0; j < 64; j++) W[j].f = wsrc[j];
    }

    // --- stage biases + W_out slice ---
    for (int i = tid; i < 512; i += 256) { sbhh[i] = b_hh[i]; sbih[i] = b_ih[i]; }
    sbout[tid] = b_out[tid];  // 256 threads, 256 values
    #pragma unroll
    for (int i = 0; i < 32; i++) {                 // 8192 float2
        int e = tid + 256 * i;
        int r = e >> 8, cc = e & 255;
        float2 v = *(const float2*)(W_out + (size_t)(cg * 32 + r) * HH + 2 * cc);
        *(float2*)(wouts + r * HP + 2 * cc) = v;
    }

    int L[8];
    #pragma unroll
    for (int r = 0; r < 8; r++) L[r] = lengths[b_base + r];

    // --- zero h0 (this CTA's tile) ---
    __stcg(&g_hbuf[0][(b_base + r0    ) * HH + col_c], 0.f);
    __stcg(&g_hbuf[0][(b_base + r0 + 4) * HH + col_c], 0.f);
    grid_barrier();

    int cur = 0;

    // =================== encoder ===================
    for (int t = 0; t < TT; t++) {
        unsigned act = 0;
        #pragma unroll
        for (int r = 0; r < 8; r++) act |= (t < L[r]) ? (1u << r) : 0u;

        if (act) {
            // prefetch xp for this thread's two outputs
            float xp0 = g_xproj[((size_t)(b_base + r0    ) * TT + t) * HH + col_c];
            float xp1 = g_xproj[((size_t)(b_base + r0 + 4) * TT + t) * HH + col_c];

            // stage h rows (L2, coherent across SMs)
            #pragma unroll
            for (int i = 0; i < 8; i++) {          // 2048 float2
                int e = tid + 256 * i;
                int r = e >> 8, cc = e & 255;
                float2 v = __ldcg(((const float2*)(g_hbuf[cur] + (b_base + r) * HH)) + cc);
                *(float2*)(hs + r * HP + 2 * cc) = v;
            }
            __syncthreads();

            #pragma unroll 1
            for (int r = 0; r < 8; r++) {
                if (act & (1u << r)) {
                    const float2* hrow = (const float2*)(hs + r * HP + kq * 128);
                    U64 a0, a1; a0.u = 0ULL; a1.u = 0ULL;
                    #pragma unroll
                    for (int j = 0; j < 64; j += 2) {
                        U64 h0v, h1v;
                        h0v.f = hrow[j];
                        h1v.f = hrow[j + 1];
                        ffma2(a0, h0v, W[j]);
                        ffma2(a1, h1v, W[j + 1]);
                    }
                    part[kq * 512 + r * 64 + c] = a0.f.x + a0.f.y + a1.f.x + a1.f.y;
                }
            }
            __syncthreads();

            #pragma unroll
            for (int q = 0; q < 2; q++) {
                int r = r0 + 4 * q;
                float v;
                if (act & (1u << r)) {
                    int o = r * 64 + c;
                    float s = part[o] + part[512 + o] + part[1024 + o] + part[1536 + o]
                            + (q ? xp1 : xp0) + sbhh[col_c];
                    v = tanhf(s);
                } else {
                    v = hs[r * HP + col_c];
                }
                __stcg(&g_hbuf[cur ^ 1][(b_base + r) * HH + col_c], v);
            }
        } else {
            // whole tile frozen: copy through
            #pragma unroll
            for (int q = 0; q < 2; q++) {
                int r = r0 + 4 * q;
                float v = __ldcg(&g_hbuf[cur][(b_base + r) * HH + col_c]);
                __stcg(&g_hbuf[cur ^ 1][(b_base + r) * HH + col_c], v);
            }
        }
        cur ^= 1;
        grid_barrier();
    }

    // =================== decoder ===================
    // stage final encoder h
    #pragma unroll
    for (int i = 0; i < 8; i++) {
        int e = tid + 256 * i;
        int r = e >> 8, cc = e & 255;
        float2 v = __ldcg(((const float2*)(g_hbuf[cur] + (b_base + r) * HH)) + cc);
        *(float2*)(hs + r * HP + 2 * cc) = v;
    }
    __syncthreads();

    for (int s = 0; s < LOUT; s++) {
        // h' = tanh(b_ih + h @ W_hh^T + b_hh)
        #pragma unroll 1
        for (int r = 0; r < 8; r++) {
            const float2* hrow = (const float2*)(hs + r * HP + kq * 128);
            U64 a0, a1; a0.u = 0ULL; a1.u = 0ULL;
            #pragma unroll
            for (int j = 0; j < 64; j += 2) {
                U64 h0v, h1v;
                h0v.f = hrow[j];
                h1v.f = hrow[j + 1];
                ffma2(a0, h0v, W[j]);
                ffma2(a1, h1v, W[j + 1]);
            }
            part[kq * 512 + r * 64 + c] = a0.f.x + a0.f.y + a1.f.x + a1.f.y;
        }
        __syncthreads();
        #pragma unroll
        for (int q = 0; q < 2; q++) {
            int r = r0 + 4 * q;
            int o = r * 64 + c;
            float sv = part[o] + part[512 + o] + part[1024 + o] + part[1536 + o]
                     + sbih[col_c] + sbhh[col_c];
            __stcg(&g_hbuf[cur ^ 1][(b_base + r) * HH + col_c], tanhf(sv));
        }
        cur ^= 1;
        grid_barrier();

        // stage the new h (full rows)
        #pragma unroll
        for (int i = 0; i < 8; i++) {
            int e = tid + 256 * i;
            int r = e >> 8, cc = e & 255;
            float2 v = __ldcg(((const float2*)(g_hbuf[cur] + (b_base + r) * HH)) + cc);
            *(float2*)(hs + r * HP + 2 * cc) = v;
        }
        __syncthreads();

        // out[b, s, :] tile: rows b_base..+8, cols o = cg*32..+32
        {
            const int rr = tid >> 5;       // 0..7
            const int oo = tid & 31;       // 0..31
            const float2* hrow = (const float2*)(hs + rr * HP);
            const float2* wrow = (const float2*)(wouts + oo * HP);
            U64 a0, a1; a0.u = 0ULL; a1.u = 0ULL;
            #pragma unroll 8
            for (int j = 0; j < 256; j += 2) {
                U64 hv0, wv0, hv1, wv1;
                hv0.f = hrow[j];     wv0.f = wrow[j];
                hv1.f = hrow[j + 1]; wv1.f = wrow[j + 1];
                ffma2(a0, hv0, wv0);
                ffma2(a1, hv1, wv1);
            }
            float val = a0.f.x + a0.f.y + a1.f.x + a1.f.y + sbout[cg * 32 + oo];
            out[((size_t)(b_base + rr) * LOUT + s) * OO + cg * 32 + oo] = val;
        }
        // no extra sync needed: next GEMM only reads hs (unchanged) and writes part,
        // whose previous readers finished before grid_barrier above.
        __syncthreads();
    }
}

// ---------------- launch ----------------
extern "C" void kernel_launch(void* const* d_in, const int* in_sizes, int n_in,
                              void* d_out, int out_size)
{
    int k = 0;
    const float* x       = (const float*)d_in[k++];
    const int*   lengths = (const int*)  d_in[k++];
    if (k < n_in && in_sizes[k] == 1) k++;           // out_lengths scalar (if present)
    const float* W_ih    = (const float*)d_in[k++];
    const float* b_ih    = (const float*)d_in[k++];
    const float* W_hh    = (const float*)d_in[k++];
    const float* b_hh    = (const float*)d_in[k++];
    const float* W_out   = (const float*)d_in[k++];
    const float* b_out   = (const float*)d_in[k++];
    float* out = (float*)d_out;

    cudaFuncSetAttribute(k_xproj, cudaFuncAttributeMaxDynamicSharedMemorySize, XPROJ_SMEM);
    cudaFuncSetAttribute(k_rnn,   cudaFuncAttributeMaxDynamicSharedMemorySize, RNN_SMEM);

    dim3 g1(HH / 64, TT / 64, BB);   // (8, 16, 128)
    k_xproj<<<g1, 256, XPROJ_SMEM>>>(x, lengths, W_ih, b_ih);
    k_rnn<<<NCTA, 256, RNN_SMEM>>>(lengths, W_hh, b_hh, b_ih, W_out, b_out, out);
}